// round 5
// baseline (speedup 1.0000x reference)
#include <cuda_runtime.h>
#include <math.h>

#define SEGS     512
#define MAXD     512
#define NTBL     7            // pos 0+1 share a map -> pre-summed into table 0
#define WDIM     512
#define HDIM     512
#define BATCH    16
#define CHAN     3
#define NW       1025
#define TBL_LEN  (NTBL * SEGS)        // 3584 float2 entries per region

// Magic constants for branch-free floor via float bit pattern
#define MAGIC    12582912.0f          // 1.5 * 2^23
#define MAGICBITS 0x4B400000u         // bit pattern of 12582912.0f
#define CLAMP_HI 0x1.fe8002p+8f       // 510.5 + 2^-15
#define CLAMP_LO (-0.5f)

struct PosConsts {
    float Cx[NTBL];
    float Cy[NTBL];
    float D [NTBL];              // includes the -0.5 midpoint shift
};

// Midpoint-centered per-segment quadratics, 1/8 folded in:
//   val(v) = C' + v*(B' + v*A),  v = xs - sid - 0.5
//   A  = 0.125*(2*(w0+w2) - 4*w1),  B' = 0.125*(w2-w0),  C' = 0.125*w1
// Layout per channel: [0,3584) = (A,B') pairs; [3584,7168) = (C', unused)
__device__ float2 g_tab[CHAN * 2 * TBL_LEN];

__device__ __forceinline__ void coef_from_w(const float* w, float& A, float& B, float& C)
{
    float w0 = w[0], w1 = w[1], w2 = w[2];
    A = 0.125f * (2.f * (w0 + w2) - 4.f * w1);
    B = 0.125f * (w2 - w0);
    C = 0.125f * w1;
}

__global__ __launch_bounds__(256)
void prep_coef_kernel(const float* __restrict__ wts)
{
    int idx = blockIdx.x * 256 + threadIdx.x;           // [0, 3*7*512)
    if (idx >= CHAN * TBL_LEN) return;
    int s   = idx & (SEGS - 1);
    int ct  = idx >> 9;
    int c   = ct / NTBL;
    int tbl = ct - c * NTBL;

    float A, B, C;
    if (tbl == 0) {                                      // pos 0 + pos 1 summed
        float A0, B0, C0, A1, B1, C1;
        coef_from_w(wts + (0 * CHAN + c) * NW + 2 * s, A0, B0, C0);
        coef_from_w(wts + (1 * CHAN + c) * NW + 2 * s, A1, B1, C1);
        A = A0 + A1; B = B0 + B1; C = C0 + C1;
    } else {
        int pos = tbl + 1;                               // 2..7
        coef_from_w(wts + (pos * CHAN + c) * NW + 2 * s, A, B, C);
    }
    int o = c * 2 * TBL_LEN + tbl * SEGS + s;
    g_tab[o]           = make_float2(A, B);
    g_tab[o + TBL_LEN] = make_float2(C, 0.f);
}

__global__ __launch_bounds__(512, 3)
void stripe_poly_kernel(const float* __restrict__ x,
                        float* __restrict__ out,
                        PosConsts pc)
{
    extern __shared__ float2 sT[];                       // 7168 float2 = 56 KB

    const int c = blockIdx.y;

    for (int k = threadIdx.x; k < 2 * TBL_LEN; k += 512)
        sT[k] = g_tab[c * 2 * TBL_LEN + k];
    __syncthreads();

    const int pixel = blockIdx.x * 512 + threadIdx.x;    // grid.x*512 == 512*512
    const float wx = (float)(pixel >> 9);
    const float hy = (float)(pixel & 511);

    float P[NTBL];
#pragma unroll
    for (int i = 0; i < NTBL; i++)
        P[i] = fmaf(pc.Cx[i], wx, fmaf(pc.Cy[i], hy, pc.D[i]));

#pragma unroll 2
    for (int b = 0; b < BATCH; b++) {
        const int eidx = ((b * CHAN + c) << 18) + pixel;
        const float xv = x[eidx];
        float accU = 0.f, accC = 0.f;
#pragma unroll
        for (int i = 0; i < NTBL; i++) {
            float ys = fmaf(0.5f, xv, P[i]);             // xs - 0.5
            float yc = fminf(fmaxf(ys, CLAMP_LO), CLAMP_HI);
            float g  = __fadd_rn(yc, MAGIC);             // 12582912 + k (RNE)
            float sfk= __fadd_rn(g, -MAGIC);             // exact float k
            float v  = ys - sfk;                         // centered local coord
            unsigned idx = __float_as_uint(g)
                         + ((unsigned)(i * SEGS) - MAGICBITS);  // wraps to i*512+k
            float2 ab = sT[idx];
            float  cc = sT[idx + TBL_LEN].x;
            accC += cc;
            accU = fmaf(v, fmaf(v, ab.x, ab.y), accU);
        }
        out[eidx] = accU + accC;
    }
}

extern "C" void kernel_launch(void* const* d_in, const int* in_sizes, int n_in,
                              void* d_out, int out_size)
{
    const float* x   = (const float*)d_in[0];   // [16, 3, 512, 512]
    const float* wts = (const float*)d_in[1];   // [8, 3, 1025]
    float* out = (float*)d_out;

    // Fold position maps analytically (host, double precision):
    //   xs = 0.5*x + (r - rmin)*S,  S = RATIO*512/dr,  r = cx*w + sgn*cy*h
    //   D additionally absorbs the -0.5 midpoint shift (ys = xs - 0.5).
    PosConsts pc;
    const double RATIO = (double)MAXD / (double)(MAXD + 1);
    for (int rot = 0; rot < 4; rot++) {
        double theta = (M_PI / 2.0) * ((double)rot / 4.0);
        double cx = cos(theta), cy = sin(theta);
        for (int s = 0; s < 2; s++) {
            int pos = rot * 2 + s;
            int tbl = (pos <= 1) ? 0 : pos - 1;          // pos 0,1 -> table 0
            double sgn  = (s == 0) ? 1.0 : -1.0;
            double rmin = (s == 0) ? 0.0 : -cy * (HDIM - 1);
            double rmax = (s == 0) ? (cx + cy) * (WDIM - 1) : cx * (WDIM - 1);
            double dr   = rmax - rmin;
            double S    = RATIO * (double)MAXD / dr;
            pc.Cx[tbl] = (float)(cx * S);
            pc.Cy[tbl] = (float)(sgn * cy * S);
            pc.D [tbl] = (float)(-rmin * S - 0.5);
        }
    }

    prep_coef_kernel<<<(CHAN * TBL_LEN + 255) / 256, 256>>>(wts);

    const int smem = 2 * TBL_LEN * sizeof(float2);       // 56 KB
    cudaFuncSetAttribute(stripe_poly_kernel,
                         cudaFuncAttributeMaxDynamicSharedMemorySize, smem);
    dim3 grid(WDIM * HDIM / 512, CHAN, 1);               // (512, 3)
    stripe_poly_kernel<<<grid, 512, smem>>>(x, out, pc);
}